// round 12
// baseline (speedup 1.0000x reference)
#include <cuda_runtime.h>
#include <cuda_fp16.h>
#include <math.h>
#include <stdint.h>

#define NN   10000
#define EE   160000
#define FIN  2208
#define KP1  2240          // FIN padded to multiple of 32
#define HH   512
#define CC   2
#define NNZ  (EE + NN)

// ---------------- scratch (static device globals; no allocation) ----------------
__device__ float g_bufB[NN * HH];                 // agg3 fp32 output
__device__ float g_t[NN * CC];
__device__ int   g_degi[NN];
__device__ float g_dinv[NN];
__device__ int   g_rowptr[NN + 1];
__device__ int   g_cursor[NN];
__device__ int   g_colsrc[NNZ];
__device__ float g_w[NNZ];
__device__ __align__(16) __half g_Ah[NN * KP1];   // GEMM A operand (fp16)
__device__ __align__(16) __half g_H[NN * HH];     // GEMM fp16 output
__device__ __align__(16) __half g_Bh[HH * KP1];   // W^T fp16, [N][Kpad] K-major

// ---------------- PTX helpers (sm_80-baseline, compile at compute_103) ----------
__device__ __forceinline__ uint32_t smem_u32(const void* p) {
    uint32_t a;
    asm("{ .reg .u64 t; cvta.to.shared.u64 t, %1; cvt.u32.u64 %0, t; }" : "=r"(a) : "l"(p));
    return a;
}
__device__ __forceinline__ void cpa16(uint32_t s, const void* g, int sz) {
    asm volatile("cp.async.cg.shared.global [%0], [%1], 16, %2;"
                 :: "r"(s), "l"(g), "r"(sz) : "memory");
}
__device__ __forceinline__ void cpa_commit() {
    asm volatile("cp.async.commit_group;" ::: "memory");
}
template <int N> __device__ __forceinline__ void cpa_wait() {
    asm volatile("cp.async.wait_group %0;" :: "n"(N) : "memory");
}
__device__ __forceinline__ void ldsm4(uint32_t& r0, uint32_t& r1, uint32_t& r2, uint32_t& r3,
                                      uint32_t addr) {
    asm volatile("ldmatrix.sync.aligned.m8n8.x4.shared.b16 {%0,%1,%2,%3}, [%4];"
                 : "=r"(r0), "=r"(r1), "=r"(r2), "=r"(r3) : "r"(addr));
}
__device__ __forceinline__ void mma16816(float* d, const uint32_t* a, const uint32_t* b) {
    asm volatile(
        "mma.sync.aligned.m16n8k16.row.col.f32.f16.f16.f32 "
        "{%0,%1,%2,%3}, {%4,%5,%6,%7}, {%8,%9}, {%0,%1,%2,%3};"
        : "+f"(d[0]), "+f"(d[1]), "+f"(d[2]), "+f"(d[3])
        : "r"(a[0]), "r"(a[1]), "r"(a[2]), "r"(a[3]), "r"(b[0]), "r"(b[1]));
}

// ---------------- graph preprocessing ----------------
__global__ void init_deg_kernel() {
    int i = blockIdx.x * blockDim.x + threadIdx.x;
    if (i < NN) g_degi[i] = 1;
}
__global__ void count_deg_kernel(const int* __restrict__ ei) {
    int e = blockIdx.x * blockDim.x + threadIdx.x;
    if (e < EE) atomicAdd(&g_degi[ei[EE + e]], 1);
}
// 1024 threads, 10 elements/thread, warp-shuffle block scan (3 syncthreads)
__global__ void scan_kernel() {
    int tid = threadIdx.x;
    int lane = tid & 31, w = tid >> 5;
    int base = tid * 10;
    int deg[10];
    int s = 0;
#pragma unroll
    for (int j = 0; j < 10; j++) {
        int i = base + j;
        deg[j] = (i < NN) ? g_degi[i] : 0;
        s += deg[j];
    }
    int inc = s;
#pragma unroll
    for (int off = 1; off < 32; off <<= 1) {
        int t = __shfl_up_sync(0xFFFFFFFFu, inc, off);
        if (lane >= off) inc += t;
    }
    __shared__ int wsum[32];
    if (lane == 31) wsum[w] = inc;
    __syncthreads();
    if (w == 0) {
        int v = wsum[lane];
        int vi = v;
#pragma unroll
        for (int off = 1; off < 32; off <<= 1) {
            int t = __shfl_up_sync(0xFFFFFFFFu, vi, off);
            if (lane >= off) vi += t;
        }
        wsum[lane] = vi - v;        // exclusive warp base
    }
    __syncthreads();
    int run = wsum[w] + inc - s;    // thread exclusive prefix
#pragma unroll
    for (int j = 0; j < 10; j++) {
        int i = base + j;
        if (i < NN) {
            g_rowptr[i] = run;
            g_cursor[i] = run;
            g_dinv[i]   = rsqrtf((float)deg[j]);
            run += deg[j];
        }
    }
    if (base < NN && base + 10 >= NN) g_rowptr[NN] = run;   // total = NNZ
}
__global__ void fill_csr_kernel(const int* __restrict__ ei) {
    int e = blockIdx.x * blockDim.x + threadIdx.x;
    if (e < EE) {
        int s = ei[e], d = ei[EE + e];
        int slot = atomicAdd(&g_cursor[d], 1);
        g_colsrc[slot] = s;
        g_w[slot] = g_dinv[s] * g_dinv[d];
    } else if (e < EE + NN) {
        int i = e - EE;
        int slot = atomicAdd(&g_cursor[i], 1);
        g_colsrc[slot] = i;
        g_w[slot] = g_dinv[i] * g_dinv[i];
    }
}

// ---------------- conversion ----------------
__global__ void convA_kernel(const float* __restrict__ src, int Kin, int Kpad) {
    int k = blockIdx.x * blockDim.x + threadIdx.x;
    int m = blockIdx.y;
    if (k >= Kpad) return;
    float v = (k < Kin) ? src[(size_t)m * Kin + k] : 0.f;
    g_Ah[(size_t)m * Kpad + k] = __float2half(v);
}
__global__ void convB_kernel(const float* __restrict__ W, int Kin, int Kpad) {
    int k = blockIdx.x * blockDim.x + threadIdx.x;
    int n = blockIdx.y;
    if (k >= Kpad) return;
    float v = (k < Kin) ? W[(size_t)k * HH + n] : 0.f;
    g_Bh[(size_t)n * Kpad + k] = __float2half(v);
}

// ---------------- MMA GEMM: H[M,512] = A @ B^T (fp16 in, fp32 acc, fp16 out) -----
// BM=128, BN=128, BK=32; 256 threads = 8 warps (2M x 4N), warp tile 64x32.
// per stage: A 8K | B 8K = 16K; 3-stage pipeline = 48K.
#define STG 16384
#define OFF_B 8192
// swizzled byte offset for (row, 16B-seg) in a 64B-pitch tile
#define SWZ(r, s) (((r) << 6) + ((((s) ^ (((r) >> 1) & 3))) << 4))

__device__ __forceinline__ void issue_chunk(
    uint32_t sb, int stage, int k0, int tid, int rowBase, int colBase, int M, int Kpad,
    const __half* Ah, const __half* Bh)
{
    uint32_t st = sb + stage * STG;
#pragma unroll
    for (int s = 0; s < 2; s++) {                 // A: 512 segs, 2/thread
        int idx = tid + s * 256;
        int r = idx >> 2, kseg = idx & 3;
        int grow = rowBase + r;
        int valid = (grow < M);
        size_t goff = (size_t)(valid ? grow : 0) * Kpad + k0 + kseg * 8;
        cpa16(st + SWZ(r, kseg), Ah + goff, valid ? 16 : 0);
    }
#pragma unroll
    for (int s = 0; s < 2; s++) {                 // B: 512 segs, 2/thread
        int idx = tid + s * 256;
        int r = idx >> 2, kseg = idx & 3;
        size_t goff = (size_t)(colBase + r) * Kpad + k0 + kseg * 8;
        cpa16(st + OFF_B + SWZ(r, kseg), Bh + goff, 16);
    }
}

__global__ __launch_bounds__(256) void mma_gemm_kernel(
    const __half* __restrict__ Ah, const __half* __restrict__ Bh,
    __half* __restrict__ H, int M, int Kpad)
{
    extern __shared__ char smem[];
    uint32_t sb = smem_u32(smem);
    int tid = threadIdx.x, lane = tid & 31, wid = tid >> 5;
    int wm = wid >> 2, wn = wid & 3;              // 2M x 4N
    int rowBase = blockIdx.y * 128, colBase = blockIdx.x * 128;
    int NC = Kpad >> 5;

    float d[4][4][4];
#pragma unroll
    for (int i = 0; i < 4; i++)
#pragma unroll
        for (int j = 0; j < 4; j++)
#pragma unroll
            for (int k = 0; k < 4; k++) d[i][j][k] = 0.f;

    issue_chunk(sb, 0, 0, tid, rowBase, colBase, M, Kpad, Ah, Bh);
    cpa_commit();
    issue_chunk(sb, 1, 32, tid, rowBase, colBase, M, Kpad, Ah, Bh);
    cpa_commit();

    // per-lane ldmatrix address components (row/seg within tile)
    int a_r = (lane & 7) + (((lane >> 3) & 1) << 3);   // + mt*16 + wm*64
    int a_s = lane >> 4;                               // + ks*2
    int b_r = (lane & 7) + ((lane >> 4) << 3);         // + h*16 + wn*32
    int b_s = (lane >> 3) & 1;                         // + ks*2

    for (int i = 0; i < NC; i++) {
        if (i + 2 < NC)
            issue_chunk(sb, (i + 2) % 3, (i + 2) << 5, tid, rowBase, colBase, M, Kpad,
                        Ah, Bh);
        cpa_commit();                 // constant group accounting
        cpa_wait<2>();                // stage i complete
        __syncthreads();
        uint32_t st = sb + (i % 3) * STG;
#pragma unroll
        for (int ks = 0; ks < 2; ks++) {
            uint32_t ah[4][4], bh[4][2];
#pragma unroll
            for (int mt = 0; mt < 4; mt++) {
                int row = wm * 64 + mt * 16 + a_r;
                uint32_t off = SWZ(row, ks * 2 + a_s);
                ldsm4(ah[mt][0], ah[mt][1], ah[mt][2], ah[mt][3], st + off);
            }
#pragma unroll
            for (int h = 0; h < 2; h++) {
                int n = wn * 32 + h * 16 + b_r;
                uint32_t off = SWZ(n, ks * 2 + b_s);
                uint32_t r0, r1, r2, r3;
                ldsm4(r0, r1, r2, r3, st + OFF_B + off);
                bh[h * 2][0] = r0; bh[h * 2][1] = r1;
                bh[h * 2 + 1][0] = r2; bh[h * 2 + 1][1] = r3;
            }
#pragma unroll
            for (int mt = 0; mt < 4; mt++)
#pragma unroll
                for (int nt = 0; nt < 4; nt++)
                    mma16816(d[mt][nt], ah[mt], bh[nt]);
        }
        __syncthreads();
    }

    // epilogue: fp16 output
#pragma unroll
    for (int mt = 0; mt < 4; mt++)
#pragma unroll
        for (int nt = 0; nt < 4; nt++) {
            int rg = rowBase + wm * 64 + mt * 16 + (lane >> 2);
            int cg = colBase + wn * 32 + nt * 8 + (lane & 3) * 2;
            if (rg < M)
                *(__half2*)&H[(size_t)rg * HH + cg] = __floats2half2_rn(d[mt][nt][0], d[mt][nt][1]);
            if (rg + 8 < M)
                *(__half2*)&H[(size_t)(rg + 8) * HH + cg] = __floats2half2_rn(d[mt][nt][2], d[mt][nt][3]);
        }
}

// ---------------- aggregation: fp16 gather, fp32 acc, +bias +relu ---------------
// mode 0: write fp32 to outf; mode 1: write fp16 (pitch 512) to g_Ah
__global__ __launch_bounds__(256) void aggregate512_kernel(
    const __half* __restrict__ in, float* __restrict__ outf,
    const float* __restrict__ bias, int do_relu, int mode)
{
    int gw = (blockIdx.x * blockDim.x + threadIdx.x) >> 5;
    int lane = threadIdx.x & 31;
    if (gw >= NN) return;
    int beg = g_rowptr[gw], end = g_rowptr[gw + 1];

    float acc[16];
#pragma unroll
    for (int j = 0; j < 16; j++) acc[j] = 0.f;

    int e = beg;
    for (; e + 2 <= end; e += 2) {      // 2-edge unroll: 4 outstanding uint4 loads
        int c0 = g_colsrc[e], c1 = g_colsrc[e + 1];
        float w0 = g_w[e], w1 = g_w[e + 1];
        const uint4* r0 = (const uint4*)(in + (size_t)c0 * HH);
        const uint4* r1 = (const uint4*)(in + (size_t)c1 * HH);
        uint4 x0 = r0[lane],      y0 = r1[lane];
        uint4 x1 = r0[32 + lane], y1 = r1[32 + lane];
        const __half2* px0 = (const __half2*)&x0;
        const __half2* px1 = (const __half2*)&x1;
        const __half2* py0 = (const __half2*)&y0;
        const __half2* py1 = (const __half2*)&y1;
#pragma unroll
        for (int j = 0; j < 4; j++) {
            float2 f0 = __half22float2(px0[j]);
            float2 f1 = __half22float2(px1[j]);
            float2 g0 = __half22float2(py0[j]);
            float2 g1 = __half22float2(py1[j]);
            acc[2 * j + 0]     += w0 * f0.x + w1 * g0.x;
            acc[2 * j + 1]     += w0 * f0.y + w1 * g0.y;
            acc[8 + 2 * j + 0] += w0 * f1.x + w1 * g1.x;
            acc[8 + 2 * j + 1] += w0 * f1.y + w1 * g1.y;
        }
    }
    if (e < end) {
        int c = g_colsrc[e];
        float w = g_w[e];
        const uint4* row = (const uint4*)(in + (size_t)c * HH);
        uint4 v0 = row[lane], v1 = row[32 + lane];
        const __half2* p0 = (const __half2*)&v0;
        const __half2* p1 = (const __half2*)&v1;
#pragma unroll
        for (int j = 0; j < 4; j++) {
            float2 f0 = __half22float2(p0[j]);
            float2 f1 = __half22float2(p1[j]);
            acc[2 * j + 0]     += w * f0.x;
            acc[2 * j + 1]     += w * f0.y;
            acc[8 + 2 * j + 0] += w * f1.x;
            acc[8 + 2 * j + 1] += w * f1.y;
        }
    }

#pragma unroll
    for (int h = 0; h < 2; h++) {
        int f = h * 256 + lane * 8;
        float r[8];
#pragma unroll
        for (int j = 0; j < 8; j++) {
            r[j] = acc[h * 8 + j] + bias[f + j];
            if (do_relu) r[j] = fmaxf(r[j], 0.f);
        }
        if (mode == 0) {
            *(float4*)&outf[(size_t)gw * HH + f]     = make_float4(r[0], r[1], r[2], r[3]);
            *(float4*)&outf[(size_t)gw * HH + f + 4] = make_float4(r[4], r[5], r[6], r[7]);
        } else {
            __half2 o[4];
#pragma unroll
            for (int j = 0; j < 4; j++) o[j] = __floats2half2_rn(r[2 * j], r[2 * j + 1]);
            *(uint4*)&g_Ah[(size_t)gw * HH + f] = *(uint4*)o;
        }
    }
}

// ---------------- layer 4 + finalize ----------------
__global__ __launch_bounds__(256) void gemm_small_kernel(
    const float* __restrict__ h, const float* __restrict__ W4, float* __restrict__ t)
{
    __shared__ float w[HH * CC];
    int tid = threadIdx.x;
    for (int i = tid; i < HH * CC; i += blockDim.x) w[i] = W4[i];
    __syncthreads();
    int gw = (blockIdx.x * blockDim.x + tid) >> 5;
    int lane = tid & 31;
    if (gw >= NN) return;
    float a0 = 0.f, a1 = 0.f;
    const float* hr = h + (size_t)gw * HH;
    for (int k = lane; k < HH; k += 32) {
        float hv = hr[k];
        a0 += hv * w[2 * k + 0];
        a1 += hv * w[2 * k + 1];
    }
#pragma unroll
    for (int off = 16; off > 0; off >>= 1) {
        a0 += __shfl_down_sync(0xFFFFFFFFu, a0, off);
        a1 += __shfl_down_sync(0xFFFFFFFFu, a1, off);
    }
    if (lane == 0) { t[gw * 2 + 0] = a0; t[gw * 2 + 1] = a1; }
}

__global__ void finalize_kernel(const float* __restrict__ t,
                                const float* __restrict__ b4,
                                float* __restrict__ out)
{
    int i = blockIdx.x * blockDim.x + threadIdx.x;
    if (i >= NN) return;
    float z0 = 0.f, z1 = 0.f;
    int beg = g_rowptr[i], end = g_rowptr[i + 1];
    for (int e = beg; e < end; e++) {
        int c = g_colsrc[e];
        float w = g_w[e];
        z0 += w * t[2 * c + 0];
        z1 += w * t[2 * c + 1];
    }
    z0 += b4[0]; z1 += b4[1];
    float m = fmaxf(z0, z1);
    float lse = m + logf(expf(z0 - m) + expf(z1 - m));
    out[2 * i + 0] = z0 - lse;
    out[2 * i + 1] = z1 - lse;
}

// ---------------- launch ----------------
extern "C" void kernel_launch(void* const* d_in, const int* in_sizes, int n_in,
                              void* d_out, int out_size)
{
    const float* x  = (const float*)d_in[0];
    const int*   ei = (const int*)d_in[1];
    const float* W1 = (const float*)d_in[3];
    const float* b1 = (const float*)d_in[4];
    const float* W2 = (const float*)d_in[5];
    const float* b2 = (const float*)d_in[6];
    const float* W3 = (const float*)d_in[7];
    const float* b3 = (const float*)d_in[8];
    const float* W4 = (const float*)d_in[9];
    const float* b4 = (const float*)d_in[10];
    float* out = (float*)d_out;

    float *pB, *pT;
    __half *pAh, *pBh, *pH;
    cudaGetSymbolAddress((void**)&pB,  g_bufB);
    cudaGetSymbolAddress((void**)&pT,  g_t);
    cudaGetSymbolAddress((void**)&pAh, g_Ah);
    cudaGetSymbolAddress((void**)&pBh, g_Bh);
    cudaGetSymbolAddress((void**)&pH,  g_H);

    // graph preprocessing
    init_deg_kernel<<<(NN + 255) / 256, 256>>>();
    count_deg_kernel<<<(EE + 255) / 256, 256>>>(ei);
    scan_kernel<<<1, 1024>>>();
    fill_csr_kernel<<<(NNZ + 255) / 256, 256>>>(ei);

    dim3 gemm_grid(HH / 128, (NN + 127) / 128);    // (4, 79)
    const int gemm_smem = 3 * STG;                 // 48 KB
    int agg_blocks = (NN * 32 + 255) / 256;

    dim3 cvA1((KP1 + 255) / 256, NN);
    dim3 cvB1((KP1 + 255) / 256, HH);
    dim3 cvB2((HH + 255) / 256, HH);

    // layer 1
    convA_kernel<<<cvA1, 256>>>(x, FIN, KP1);
    convB_kernel<<<cvB1, 256>>>(W1, FIN, KP1);
    mma_gemm_kernel<<<gemm_grid, 256, gemm_smem>>>(pAh, pBh, pH, NN, KP1);
    aggregate512_kernel<<<agg_blocks, 256>>>(pH, pB, b1, 1, 1);   // -> fp16 g_Ah
    // layer 2
    convB_kernel<<<cvB2, 256>>>(W2, HH, HH);
    mma_gemm_kernel<<<gemm_grid, 256, gemm_smem>>>(pAh, pBh, pH, NN, HH);
    aggregate512_kernel<<<agg_blocks, 256>>>(pH, pB, b2, 1, 1);   // -> fp16 g_Ah
    // layer 3
    convB_kernel<<<cvB2, 256>>>(W3, HH, HH);
    mma_gemm_kernel<<<gemm_grid, 256, gemm_smem>>>(pAh, pBh, pH, NN, HH);
    aggregate512_kernel<<<agg_blocks, 256>>>(pH, pB, b3, 1, 0);   // -> fp32 bufB
    // layer 4 + log_softmax
    gemm_small_kernel<<<agg_blocks, 256>>>(pB, W4, pT);
    finalize_kernel<<<(NN + 255) / 256, 256>>>(pT, b4, out);
}

// round 14
// speedup vs baseline: 1.0485x; 1.0485x over previous
#include <cuda_runtime.h>
#include <cuda_fp16.h>
#include <math.h>
#include <stdint.h>

#define NN   10000
#define EE   160000
#define FIN  2208
#define KP1  2240          // FIN padded to multiple of 32
#define HH   512
#define CC   2
#define NNZ  (EE + NN)

// ---------------- scratch (static device globals; no allocation) ----------------
__device__ float g_bufB[NN * HH];                 // agg3 fp32 output
__device__ float g_t[NN * CC];
__device__ int   g_degi[NN];
__device__ float g_dinv[NN];
__device__ int   g_rowptr[NN + 1];
__device__ int   g_cursor[NN];
__device__ int   g_colsrc[NNZ];
__device__ float g_w[NNZ];
__device__ __align__(16) __half g_Ah[NN * KP1];   // GEMM A operand (fp16)
__device__ __align__(16) __half g_H[NN * HH];     // GEMM fp16 output
__device__ __align__(16) __half g_Bh[HH * KP1];   // W^T fp16, [N][Kpad] K-major

// ---------------- PTX helpers (sm_80-baseline, compile at compute_103) ----------
__device__ __forceinline__ uint32_t smem_u32(const void* p) {
    uint32_t a;
    asm("{ .reg .u64 t; cvta.to.shared.u64 t, %1; cvt.u32.u64 %0, t; }" : "=r"(a) : "l"(p));
    return a;
}
__device__ __forceinline__ void cpa16(uint32_t s, const void* g, int sz) {
    asm volatile("cp.async.cg.shared.global [%0], [%1], 16, %2;"
                 :: "r"(s), "l"(g), "r"(sz) : "memory");
}
__device__ __forceinline__ void cpa_commit() {
    asm volatile("cp.async.commit_group;" ::: "memory");
}
template <int N> __device__ __forceinline__ void cpa_wait() {
    asm volatile("cp.async.wait_group %0;" :: "n"(N) : "memory");
}
__device__ __forceinline__ void ldsm4(uint32_t& r0, uint32_t& r1, uint32_t& r2, uint32_t& r3,
                                      uint32_t addr) {
    asm volatile("ldmatrix.sync.aligned.m8n8.x4.shared.b16 {%0,%1,%2,%3}, [%4];"
                 : "=r"(r0), "=r"(r1), "=r"(r2), "=r"(r3) : "r"(addr));
}
__device__ __forceinline__ void mma16816(float* d, const uint32_t* a, const uint32_t* b) {
    asm volatile(
        "mma.sync.aligned.m16n8k16.row.col.f32.f16.f16.f32 "
        "{%0,%1,%2,%3}, {%4,%5,%6,%7}, {%8,%9}, {%0,%1,%2,%3};"
        : "+f"(d[0]), "+f"(d[1]), "+f"(d[2]), "+f"(d[3])
        : "r"(a[0]), "r"(a[1]), "r"(a[2]), "r"(a[3]), "r"(b[0]), "r"(b[1]));
}

// ---------------- graph preprocessing ----------------
__global__ void init_deg_kernel() {
    int i = blockIdx.x * blockDim.x + threadIdx.x;
    if (i < NN) g_degi[i] = 1;
}
__global__ void count_deg_kernel(const int* __restrict__ ei) {
    int e = blockIdx.x * blockDim.x + threadIdx.x;
    if (e < EE) atomicAdd(&g_degi[ei[EE + e]], 1);
}
// 1024 threads, 10 elements/thread, warp-shuffle block scan (3 syncthreads)
__global__ void scan_kernel() {
    int tid = threadIdx.x;
    int lane = tid & 31, w = tid >> 5;
    int base = tid * 10;
    int deg[10];
    int s = 0;
#pragma unroll
    for (int j = 0; j < 10; j++) {
        int i = base + j;
        deg[j] = (i < NN) ? g_degi[i] : 0;
        s += deg[j];
    }
    int inc = s;
#pragma unroll
    for (int off = 1; off < 32; off <<= 1) {
        int t = __shfl_up_sync(0xFFFFFFFFu, inc, off);
        if (lane >= off) inc += t;
    }
    __shared__ int wsum[32];
    if (lane == 31) wsum[w] = inc;
    __syncthreads();
    if (w == 0) {
        int v = wsum[lane];
        int vi = v;
#pragma unroll
        for (int off = 1; off < 32; off <<= 1) {
            int t = __shfl_up_sync(0xFFFFFFFFu, vi, off);
            if (lane >= off) vi += t;
        }
        wsum[lane] = vi - v;        // exclusive warp base
    }
    __syncthreads();
    int run = wsum[w] + inc - s;    // thread exclusive prefix
#pragma unroll
    for (int j = 0; j < 10; j++) {
        int i = base + j;
        if (i < NN) {
            g_rowptr[i] = run;
            g_cursor[i] = run;
            g_dinv[i]   = rsqrtf((float)deg[j]);
            run += deg[j];
        }
    }
    if (base < NN && base + 10 >= NN) g_rowptr[NN] = run;   // total = NNZ
}
__global__ void fill_csr_kernel(const int* __restrict__ ei) {
    int e = blockIdx.x * blockDim.x + threadIdx.x;
    if (e < EE) {
        int s = ei[e], d = ei[EE + e];
        int slot = atomicAdd(&g_cursor[d], 1);
        g_colsrc[slot] = s;
        g_w[slot] = g_dinv[s] * g_dinv[d];
    } else if (e < EE + NN) {
        int i = e - EE;
        int slot = atomicAdd(&g_cursor[i], 1);
        g_colsrc[slot] = i;
        g_w[slot] = g_dinv[i] * g_dinv[i];
    }
}

// ---------------- conversion ----------------
__global__ void convA_kernel(const float* __restrict__ src, int Kin, int Kpad) {
    int k = blockIdx.x * blockDim.x + threadIdx.x;
    int m = blockIdx.y;
    if (k >= Kpad) return;
    float v = (k < Kin) ? src[(size_t)m * Kin + k] : 0.f;
    g_Ah[(size_t)m * Kpad + k] = __float2half(v);
}
__global__ void convB_kernel(const float* __restrict__ W, int Kin, int Kpad) {
    int k = blockIdx.x * blockDim.x + threadIdx.x;
    int n = blockIdx.y;
    if (k >= Kpad) return;
    float v = (k < Kin) ? W[(size_t)k * HH + n] : 0.f;
    g_Bh[(size_t)n * Kpad + k] = __float2half(v);
}

// ---------------- MMA GEMM: H[M,512] = A @ B^T (fp16 in, fp32 acc, fp16 out) -----
// BM=128, BN=64, BK=32; 256 threads = 8 warps (4Mx2N), warp tile 32x32.
// per stage: A 8K | B 4K = 12K; 4-stage pipeline = 48K. (2 CTAs/SM occupancy)
#define STG 12288
#define OFF_B 8192
// swizzled byte offset for (row, 16B-seg) in a 64B-pitch tile
#define SWZ(r, s) (((r) << 6) + ((((s) ^ (((r) >> 1) & 3))) << 4))

__device__ __forceinline__ void issue_chunk(
    uint32_t sb, int stage, int k0, int tid, int rowBase, int colBase, int M, int Kpad,
    const __half* Ah, const __half* Bh)
{
    uint32_t st = sb + stage * STG;
#pragma unroll
    for (int s = 0; s < 2; s++) {                 // A: 512 segs, 2/thread
        int idx = tid + s * 256;
        int r = idx >> 2, kseg = idx & 3;
        int grow = rowBase + r;
        int valid = (grow < M);
        size_t goff = (size_t)(valid ? grow : 0) * Kpad + k0 + kseg * 8;
        cpa16(st + SWZ(r, kseg), Ah + goff, valid ? 16 : 0);
    }
    {                                             // B: 256 segs, 1/thread
        int r = tid >> 2, kseg = tid & 3;
        size_t goff = (size_t)(colBase + r) * Kpad + k0 + kseg * 8;
        cpa16(st + OFF_B + SWZ(r, kseg), Bh + goff, 16);
    }
}

__global__ __launch_bounds__(256) void mma_gemm_kernel(
    const __half* __restrict__ Ah, const __half* __restrict__ Bh,
    __half* __restrict__ H, int M, int Kpad)
{
    extern __shared__ char smem[];
    uint32_t sb = smem_u32(smem);
    int tid = threadIdx.x, lane = tid & 31, wid = tid >> 5;
    int wm = wid >> 1, wn = wid & 1;
    int rowBase = blockIdx.y * 128, colBase = blockIdx.x * 64;
    int NC = Kpad >> 5;

    float d[2][4][4];
#pragma unroll
    for (int i = 0; i < 2; i++)
#pragma unroll
        for (int j = 0; j < 4; j++)
#pragma unroll
            for (int k = 0; k < 4; k++) d[i][j][k] = 0.f;

    issue_chunk(sb, 0, 0, tid, rowBase, colBase, M, Kpad, Ah, Bh);
    cpa_commit();
    issue_chunk(sb, 1, 32, tid, rowBase, colBase, M, Kpad, Ah, Bh);
    cpa_commit();
    issue_chunk(sb, 2, 64, tid, rowBase, colBase, M, Kpad, Ah, Bh);
    cpa_commit();

    // per-lane ldmatrix address components (row/seg within tile)
    int a_r = (lane & 7) + (((lane >> 3) & 1) << 3);   // + mt*16 + wm*32
    int a_s = lane >> 4;                               // + ks*2
    int b_r = (lane & 7) + ((lane >> 4) << 3);         // + half*16 + wn*32
    int b_s = (lane >> 3) & 1;                         // + ks*2

    for (int i = 0; i < NC; i++) {
        if (i + 3 < NC)
            issue_chunk(sb, (i + 3) & 3, (i + 3) << 5, tid, rowBase, colBase, M, Kpad,
                        Ah, Bh);
        cpa_commit();                 // constant group accounting
        cpa_wait<3>();                // stage i complete
        __syncthreads();
        uint32_t st = sb + (i & 3) * STG;
#pragma unroll
        for (int ks = 0; ks < 2; ks++) {
            uint32_t ah[2][4], bh[4][2];
#pragma unroll
            for (int mt = 0; mt < 2; mt++) {
                int row = wm * 32 + mt * 16 + a_r;
                uint32_t off = SWZ(row, ks * 2 + a_s);
                ldsm4(ah[mt][0], ah[mt][1], ah[mt][2], ah[mt][3], st + off);
            }
#pragma unroll
            for (int h = 0; h < 2; h++) {
                int n = wn * 32 + h * 16 + b_r;
                uint32_t off = SWZ(n, ks * 2 + b_s);
                uint32_t r0, r1, r2, r3;
                ldsm4(r0, r1, r2, r3, st + OFF_B + off);
                bh[h * 2][0] = r0; bh[h * 2][1] = r1;
                bh[h * 2 + 1][0] = r2; bh[h * 2 + 1][1] = r3;
            }
#pragma unroll
            for (int mt = 0; mt < 2; mt++)
#pragma unroll
                for (int nt = 0; nt < 4; nt++)
                    mma16816(d[mt][nt], ah[mt], bh[nt]);
        }
        __syncthreads();
    }

    // epilogue: fp16 output
#pragma unroll
    for (int mt = 0; mt < 2; mt++)
#pragma unroll
        for (int nt = 0; nt < 4; nt++) {
            int rg = rowBase + wm * 32 + mt * 16 + (lane >> 2);
            int cg = colBase + wn * 32 + nt * 8 + (lane & 3) * 2;
            if (rg < M)
                *(__half2*)&H[(size_t)rg * HH + cg] = __floats2half2_rn(d[mt][nt][0], d[mt][nt][1]);
            if (rg + 8 < M)
                *(__half2*)&H[(size_t)(rg + 8) * HH + cg] = __floats2half2_rn(d[mt][nt][2], d[mt][nt][3]);
        }
}

// ---------------- aggregation: fp16 gather, fp32 acc, +bias +relu ---------------
// mode 0: write fp32 to outf; mode 1: write fp16 (pitch 512) to g_Ah
__global__ __launch_bounds__(256) void aggregate512_kernel(
    const __half* __restrict__ in, float* __restrict__ outf,
    const float* __restrict__ bias, int do_relu, int mode)
{
    int gw = (blockIdx.x * blockDim.x + threadIdx.x) >> 5;
    int lane = threadIdx.x & 31;
    if (gw >= NN) return;
    int beg = g_rowptr[gw], end = g_rowptr[gw + 1];

    float acc[16];
#pragma unroll
    for (int j = 0; j < 16; j++) acc[j] = 0.f;

    int e = beg;
    for (; e + 2 <= end; e += 2) {      // 2-edge unroll: 4 outstanding uint4 loads
        int c0 = g_colsrc[e], c1 = g_colsrc[e + 1];
        float w0 = g_w[e], w1 = g_w[e + 1];
        const uint4* r0 = (const uint4*)(in + (size_t)c0 * HH);
        const uint4* r1 = (const uint4*)(in + (size_t)c1 * HH);
        uint4 x0 = r0[lane],      y0 = r1[lane];
        uint4 x1 = r0[32 + lane], y1 = r1[32 + lane];
        const __half2* px0 = (const __half2*)&x0;
        const __half2* px1 = (const __half2*)&x1;
        const __half2* py0 = (const __half2*)&y0;
        const __half2* py1 = (const __half2*)&y1;
#pragma unroll
        for (int j = 0; j < 4; j++) {
            float2 f0 = __half22float2(px0[j]);
            float2 f1 = __half22float2(px1[j]);
            float2 g0 = __half22float2(py0[j]);
            float2 g1 = __half22float2(py1[j]);
            acc[2 * j + 0]     += w0 * f0.x + w1 * g0.x;
            acc[2 * j + 1]     += w0 * f0.y + w1 * g0.y;
            acc[8 + 2 * j + 0] += w0 * f1.x + w1 * g1.x;
            acc[8 + 2 * j + 1] += w0 * f1.y + w1 * g1.y;
        }
    }
    if (e < end) {
        int c = g_colsrc[e];
        float w = g_w[e];
        const uint4* row = (const uint4*)(in + (size_t)c * HH);
        uint4 v0 = row[lane], v1 = row[32 + lane];
        const __half2* p0 = (const __half2*)&v0;
        const __half2* p1 = (const __half2*)&v1;
#pragma unroll
        for (int j = 0; j < 4; j++) {
            float2 f0 = __half22float2(p0[j]);
            float2 f1 = __half22float2(p1[j]);
            acc[2 * j + 0]     += w * f0.x;
            acc[2 * j + 1]     += w * f0.y;
            acc[8 + 2 * j + 0] += w * f1.x;
            acc[8 + 2 * j + 1] += w * f1.y;
        }
    }

#pragma unroll
    for (int h = 0; h < 2; h++) {
        int f = h * 256 + lane * 8;
        float r[8];
#pragma unroll
        for (int j = 0; j < 8; j++) {
            r[j] = acc[h * 8 + j] + bias[f + j];
            if (do_relu) r[j] = fmaxf(r[j], 0.f);
        }
        if (mode == 0) {
            *(float4*)&outf[(size_t)gw * HH + f]     = make_float4(r[0], r[1], r[2], r[3]);
            *(float4*)&outf[(size_t)gw * HH + f + 4] = make_float4(r[4], r[5], r[6], r[7]);
        } else {
            __half2 o[4];
#pragma unroll
            for (int j = 0; j < 4; j++) o[j] = __floats2half2_rn(r[2 * j], r[2 * j + 1]);
            *(uint4*)&g_Ah[(size_t)gw * HH + f] = *(uint4*)o;
        }
    }
}

// ---------------- layer 4 + finalize ----------------
__global__ __launch_bounds__(256) void gemm_small_kernel(
    const float* __restrict__ h, const float* __restrict__ W4, float* __restrict__ t)
{
    __shared__ float w[HH * CC];
    int tid = threadIdx.x;
    for (int i = tid; i < HH * CC; i += blockDim.x) w[i] = W4[i];
    __syncthreads();
    int gw = (blockIdx.x * blockDim.x + tid) >> 5;
    int lane = tid & 31;
    if (gw >= NN) return;
    float a0 = 0.f, a1 = 0.f;
    const float* hr = h + (size_t)gw * HH;
    for (int k = lane; k < HH; k += 32) {
        float hv = hr[k];
        a0 += hv * w[2 * k + 0];
        a1 += hv * w[2 * k + 1];
    }
#pragma unroll
    for (int off = 16; off > 0; off >>= 1) {
        a0 += __shfl_down_sync(0xFFFFFFFFu, a0, off);
        a1 += __shfl_down_sync(0xFFFFFFFFu, a1, off);
    }
    if (lane == 0) { t[gw * 2 + 0] = a0; t[gw * 2 + 1] = a1; }
}

__global__ void finalize_kernel(const float* __restrict__ t,
                                const float* __restrict__ b4,
                                float* __restrict__ out)
{
    int i = blockIdx.x * blockDim.x + threadIdx.x;
    if (i >= NN) return;
    float z0 = 0.f, z1 = 0.f;
    int beg = g_rowptr[i], end = g_rowptr[i + 1];
    for (int e = beg; e < end; e++) {
        int c = g_colsrc[e];
        float w = g_w[e];
        z0 += w * t[2 * c + 0];
        z1 += w * t[2 * c + 1];
    }
    z0 += b4[0]; z1 += b4[1];
    float m = fmaxf(z0, z1);
    float lse = m + logf(expf(z0 - m) + expf(z1 - m));
    out[2 * i + 0] = z0 - lse;
    out[2 * i + 1] = z1 - lse;
}

// ---------------- launch ----------------
extern "C" void kernel_launch(void* const* d_in, const int* in_sizes, int n_in,
                              void* d_out, int out_size)
{
    const float* x  = (const float*)d_in[0];
    const int*   ei = (const int*)d_in[1];
    const float* W1 = (const float*)d_in[3];
    const float* b1 = (const float*)d_in[4];
    const float* W2 = (const float*)d_in[5];
    const float* b2 = (const float*)d_in[6];
    const float* W3 = (const float*)d_in[7];
    const float* b3 = (const float*)d_in[8];
    const float* W4 = (const float*)d_in[9];
    const float* b4 = (const float*)d_in[10];
    float* out = (float*)d_out;

    float *pB, *pT;
    __half *pAh, *pBh, *pH;
    cudaGetSymbolAddress((void**)&pB,  g_bufB);
    cudaGetSymbolAddress((void**)&pT,  g_t);
    cudaGetSymbolAddress((void**)&pAh, g_Ah);
    cudaGetSymbolAddress((void**)&pBh, g_Bh);
    cudaGetSymbolAddress((void**)&pH,  g_H);

    // graph preprocessing
    init_deg_kernel<<<(NN + 255) / 256, 256>>>();
    count_deg_kernel<<<(EE + 255) / 256, 256>>>(ei);
    scan_kernel<<<1, 1024>>>();
    fill_csr_kernel<<<(NNZ + 255) / 256, 256>>>(ei);

    dim3 gemm_grid(HH / 64, (NN + 127) / 128);     // (8, 79)
    const int gemm_smem = 4 * STG;                 // 48 KB
    int agg_blocks = (NN * 32 + 255) / 256;

    dim3 cvA1((KP1 + 255) / 256, NN);
    dim3 cvB1((KP1 + 255) / 256, HH);
    dim3 cvB2((HH + 255) / 256, HH);

    // layer 1
    convA_kernel<<<cvA1, 256>>>(x, FIN, KP1);
    convB_kernel<<<cvB1, 256>>>(W1, FIN, KP1);
    mma_gemm_kernel<<<gemm_grid, 256, gemm_smem>>>(pAh, pBh, pH, NN, KP1);
    aggregate512_kernel<<<agg_blocks, 256>>>(pH, pB, b1, 1, 1);   // -> fp16 g_Ah
    // layer 2
    convB_kernel<<<cvB2, 256>>>(W2, HH, HH);
    mma_gemm_kernel<<<gemm_grid, 256, gemm_smem>>>(pAh, pBh, pH, NN, HH);
    aggregate512_kernel<<<agg_blocks, 256>>>(pH, pB, b2, 1, 1);   // -> fp16 g_Ah
    // layer 3
    convB_kernel<<<cvB2, 256>>>(W3, HH, HH);
    mma_gemm_kernel<<<gemm_grid, 256, gemm_smem>>>(pAh, pBh, pH, NN, HH);
    aggregate512_kernel<<<agg_blocks, 256>>>(pH, pB, b3, 1, 0);   // -> fp32 bufB
    // layer 4 + log_softmax
    gemm_small_kernel<<<agg_blocks, 256>>>(pB, W4, pT);
    finalize_kernel<<<(NN + 255) / 256, 256>>>(pT, b4, out);
}

// round 16
// speedup vs baseline: 1.1319x; 1.0796x over previous
#include <cuda_runtime.h>
#include <cuda_fp16.h>
#include <math.h>
#include <stdint.h>

#define NN   10000
#define EE   160000
#define FIN  2208
#define KP1  2240          // FIN padded to multiple of 64
#define HH   512
#define CC   2
#define NNZ  (EE + NN)

// ---------------- scratch (static device globals; no allocation) ----------------
__device__ float g_t[NN * CC];
__device__ int   g_degi[NN];
__device__ float g_dinv[NN];
__device__ int   g_rowptr[NN + 1];
__device__ int   g_cursor[NN];
__device__ int   g_colsrc[NNZ];
__device__ float g_w[NNZ];
__device__ __align__(16) __half g_Ah[NN * KP1];   // GEMM A operand (fp16)
__device__ __align__(16) __half g_H[NN * HH];     // GEMM fp16 output
__device__ __align__(16) __half g_Bh1[HH * KP1];  // W1^T fp16 [512][2240]
__device__ __align__(16) __half g_Bh2[HH * HH];   // W2^T fp16 [512][512]
__device__ __align__(16) __half g_Bh3[HH * HH];   // W3^T fp16 [512][512]

// ---------------- PTX helpers (sm_80-baseline, compile at compute_103) ----------
__device__ __forceinline__ uint32_t smem_u32(const void* p) {
    uint32_t a;
    asm("{ .reg .u64 t; cvta.to.shared.u64 t, %1; cvt.u32.u64 %0, t; }" : "=r"(a) : "l"(p));
    return a;
}
__device__ __forceinline__ void cpa16(uint32_t s, const void* g, int sz) {
    asm volatile("cp.async.cg.shared.global [%0], [%1], 16, %2;"
                 :: "r"(s), "l"(g), "r"(sz) : "memory");
}
__device__ __forceinline__ void cpa_commit() {
    asm volatile("cp.async.commit_group;" ::: "memory");
}
template <int N> __device__ __forceinline__ void cpa_wait() {
    asm volatile("cp.async.wait_group %0;" :: "n"(N) : "memory");
}
__device__ __forceinline__ void ldsm4(uint32_t& r0, uint32_t& r1, uint32_t& r2, uint32_t& r3,
                                      uint32_t addr) {
    asm volatile("ldmatrix.sync.aligned.m8n8.x4.shared.b16 {%0,%1,%2,%3}, [%4];"
                 : "=r"(r0), "=r"(r1), "=r"(r2), "=r"(r3) : "r"(addr));
}
__device__ __forceinline__ void mma16816(float* d, const uint32_t* a, const uint32_t* b) {
    asm volatile(
        "mma.sync.aligned.m16n8k16.row.col.f32.f16.f16.f32 "
        "{%0,%1,%2,%3}, {%4,%5,%6,%7}, {%8,%9}, {%0,%1,%2,%3};"
        : "+f"(d[0]), "+f"(d[1]), "+f"(d[2]), "+f"(d[3])
        : "r"(a[0]), "r"(a[1]), "r"(a[2]), "r"(a[3]), "r"(b[0]), "r"(b[1]));
}

// ---------------- graph preprocessing ----------------
__global__ void count_deg_kernel(const int* __restrict__ ei) {
    int e = blockIdx.x * blockDim.x + threadIdx.x;
    if (e < EE) atomicAdd(&g_degi[ei[EE + e]], 1);
}
// 1024 threads, 10 elements/thread, warp-shuffle block scan. deg = g_degi + 1 (self loop)
__global__ void scan_kernel() {
    int tid = threadIdx.x;
    int lane = tid & 31, w = tid >> 5;
    int base = tid * 10;
    int deg[10];
    int s = 0;
#pragma unroll
    for (int j = 0; j < 10; j++) {
        int i = base + j;
        deg[j] = (i < NN) ? g_degi[i] + 1 : 0;
        s += deg[j];
    }
    int inc = s;
#pragma unroll
    for (int off = 1; off < 32; off <<= 1) {
        int t = __shfl_up_sync(0xFFFFFFFFu, inc, off);
        if (lane >= off) inc += t;
    }
    __shared__ int wsum[32];
    if (lane == 31) wsum[w] = inc;
    __syncthreads();
    if (w == 0) {
        int v = wsum[lane];
        int vi = v;
#pragma unroll
        for (int off = 1; off < 32; off <<= 1) {
            int t = __shfl_up_sync(0xFFFFFFFFu, vi, off);
            if (lane >= off) vi += t;
        }
        wsum[lane] = vi - v;        // exclusive warp base
    }
    __syncthreads();
    int run = wsum[w] + inc - s;    // thread exclusive prefix
#pragma unroll
    for (int j = 0; j < 10; j++) {
        int i = base + j;
        if (i < NN) {
            g_rowptr[i] = run;
            g_cursor[i] = run;
            g_dinv[i]   = rsqrtf((float)deg[j]);
            run += deg[j];
        }
    }
    if (base < NN && base + 10 >= NN) g_rowptr[NN] = run;   // total = NNZ
}
__global__ void fill_csr_kernel(const int* __restrict__ ei) {
    int e = blockIdx.x * blockDim.x + threadIdx.x;
    if (e < EE) {
        int s = ei[e], d = ei[EE + e];
        int slot = atomicAdd(&g_cursor[d], 1);
        g_colsrc[slot] = s;
        g_w[slot] = g_dinv[s] * g_dinv[d];
    } else if (e < EE + NN) {
        int i = e - EE;
        int slot = atomicAdd(&g_cursor[i], 1);
        g_colsrc[slot] = i;
        g_w[slot] = g_dinv[i] * g_dinv[i];
    }
}

// ---------------- conversion ----------------
__global__ void convA_kernel(const float* __restrict__ src, int Kin, int Kpad) {
    int k = blockIdx.x * blockDim.x + threadIdx.x;
    int m = blockIdx.y;
    if (k >= Kpad) return;
    float v = (k < Kin) ? src[(size_t)m * Kin + k] : 0.f;
    g_Ah[(size_t)m * Kpad + k] = __float2half(v);
}
// all three weights transposed in one launch; z selects the weight
__global__ void convB_all_kernel(const float* __restrict__ W1,
                                 const float* __restrict__ W2,
                                 const float* __restrict__ W3) {
    int k = blockIdx.x * blockDim.x + threadIdx.x;
    int n = blockIdx.y;
    int z = blockIdx.z;
    if (z == 0) {
        if (k >= KP1) return;
        float v = (k < FIN) ? W1[(size_t)k * HH + n] : 0.f;
        g_Bh1[(size_t)n * KP1 + k] = __float2half(v);
    } else {
        if (k >= HH) return;
        const float* W = (z == 1) ? W2 : W3;
        __half* dst = (z == 1) ? g_Bh2 : g_Bh3;
        dst[(size_t)n * HH + k] = __float2half(W[(size_t)k * HH + n]);
    }
}

// ---------------- MMA GEMM: H[M,512] = A @ B^T (fp16 in, fp32 acc, fp16 out) -----
// BM=128, BN=64, BK=64; 256 threads = 8 warps (4Mx2N), warp tile 32x32.
// per stage: A 16K | B 8K = 24K; 3-stage pipeline = 72K (opt-in). 2 CTAs/SM.
#define STG 24576
#define OFF_B 16384
// swizzled byte offset for (row, 16B-seg) in a 128B-pitch tile (8 segs/row)
#define SWZ(r, s) (((r) << 7) + ((((s) ^ ((r) & 7))) << 4))

__device__ __forceinline__ void issue_chunk(
    uint32_t sb, int stage, int k0, int tid, int rowBase, int colBase, int M, int Kpad,
    const __half* Ah, const __half* Bh)
{
    uint32_t st = sb + stage * STG;
#pragma unroll
    for (int s = 0; s < 4; s++) {                 // A: 1024 segs, 4/thread
        int idx = tid + s * 256;
        int r = idx >> 3, kseg = idx & 7;
        int grow = rowBase + r;
        int valid = (grow < M);
        size_t goff = (size_t)(valid ? grow : 0) * Kpad + k0 + kseg * 8;
        cpa16(st + SWZ(r, kseg), Ah + goff, valid ? 16 : 0);
    }
#pragma unroll
    for (int s = 0; s < 2; s++) {                 // B: 512 segs, 2/thread
        int idx = tid + s * 256;
        int r = idx >> 3, kseg = idx & 7;
        size_t goff = (size_t)(colBase + r) * Kpad + k0 + kseg * 8;
        cpa16(st + OFF_B + SWZ(r, kseg), Bh + goff, 16);
    }
}

__global__ __launch_bounds__(256) void mma_gemm_kernel(
    const __half* __restrict__ Ah, const __half* __restrict__ Bh,
    __half* __restrict__ H, int M, int Kpad)
{
    extern __shared__ char smem[];
    uint32_t sb = smem_u32(smem);
    int tid = threadIdx.x, lane = tid & 31, wid = tid >> 5;
    int wm = wid >> 1, wn = wid & 1;
    int rowBase = blockIdx.y * 128, colBase = blockIdx.x * 64;
    int NC = Kpad >> 6;

    float d[2][4][4];
#pragma unroll
    for (int i = 0; i < 2; i++)
#pragma unroll
        for (int j = 0; j < 4; j++)
#pragma unroll
            for (int k = 0; k < 4; k++) d[i][j][k] = 0.f;

    issue_chunk(sb, 0, 0, tid, rowBase, colBase, M, Kpad, Ah, Bh);
    cpa_commit();
    issue_chunk(sb, 1, 64, tid, rowBase, colBase, M, Kpad, Ah, Bh);
    cpa_commit();

    // per-lane ldmatrix address components (row/seg within tile)
    int a_r = (lane & 7) + (((lane >> 3) & 1) << 3);   // + mt*16 + wm*32
    int a_s = lane >> 4;                               // + ks*2
    int b_r = (lane & 7) + ((lane >> 4) << 3);         // + half*16 + wn*32
    int b_s = (lane >> 3) & 1;                         // + ks*2

    for (int i = 0; i < NC; i++) {
        if (i + 2 < NC)
            issue_chunk(sb, (i + 2) % 3, (i + 2) << 6, tid, rowBase, colBase, M, Kpad,
                        Ah, Bh);
        cpa_commit();                 // constant group accounting
        cpa_wait<2>();                // stage i complete
        __syncthreads();
        uint32_t st = sb + (i % 3) * STG;
#pragma unroll
        for (int ks = 0; ks < 4; ks++) {
            uint32_t ah[2][4], bh[4][2];
#pragma unroll
            for (int mt = 0; mt < 2; mt++) {
                int row = wm * 32 + mt * 16 + a_r;
                uint32_t off = SWZ(row, ks * 2 + a_s);
                ldsm4(ah[mt][0], ah[mt][1], ah[mt][2], ah[mt][3], st + off);
            }
#pragma unroll
            for (int h = 0; h < 2; h++) {
                int n = wn * 32 + h * 16 + b_r;
                uint32_t off = SWZ(n, ks * 2 + b_s);
                uint32_t r0, r1, r2, r3;
                ldsm4(r0, r1, r2, r3, st + OFF_B + off);
                bh[h * 2][0] = r0; bh[h * 2][1] = r1;
                bh[h * 2 + 1][0] = r2; bh[h * 2 + 1][1] = r3;
            }
#pragma unroll
            for (int mt = 0; mt < 2; mt++)
#pragma unroll
                for (int nt = 0; nt < 4; nt++)
                    mma16816(d[mt][nt], ah[mt], bh[nt]);
        }
        __syncthreads();
    }

    // epilogue: fp16 output
#pragma unroll
    for (int mt = 0; mt < 2; mt++)
#pragma unroll
        for (int nt = 0; nt < 4; nt++) {
            int rg = rowBase + wm * 32 + mt * 16 + (lane >> 2);
            int cg = colBase + wn * 32 + nt * 8 + (lane & 3) * 2;
            if (rg < M)
                *(__half2*)&H[(size_t)rg * HH + cg] = __floats2half2_rn(d[mt][nt][0], d[mt][nt][1]);
            if (rg + 8 < M)
                *(__half2*)&H[(size_t)(rg + 8) * HH + cg] = __floats2half2_rn(d[mt][nt][2], d[mt][nt][3]);
        }
}

// ---------------- aggregation: fp16 gather, fp32 acc, +bias +relu ---------------
// mode 1: write fp16 (pitch 512) to g_Ah
// mode 2: fused layer-4: t[gw] = (relu(agg + b)) @ W4   (writes g_t, not g_Ah)
__global__ __launch_bounds__(256) void aggregate512_kernel(
    const __half* __restrict__ in, const float* __restrict__ bias,
    int mode, const float* __restrict__ W4)
{
    __shared__ float sw[HH * CC];
    if (mode == 2) {
        for (int i = threadIdx.x; i < HH * CC; i += blockDim.x) sw[i] = W4[i];
        __syncthreads();
    }
    int gw = (blockIdx.x * blockDim.x + threadIdx.x) >> 5;
    int lane = threadIdx.x & 31;
    if (gw >= NN) return;
    int beg = g_rowptr[gw], end = g_rowptr[gw + 1];

    float acc[16];
#pragma unroll
    for (int j = 0; j < 16; j++) acc[j] = 0.f;

    for (int e = beg; e < end; e++) {
        int c = g_colsrc[e];
        float w = g_w[e];
        const uint4* row = (const uint4*)(in + (size_t)c * HH);
        uint4 v0 = row[lane];           // features lane*8 .. +7
        uint4 v1 = row[32 + lane];      // features 256+lane*8 .. +7
        const __half2* p0 = (const __half2*)&v0;
        const __half2* p1 = (const __half2*)&v1;
#pragma unroll
        for (int j = 0; j < 4; j++) {
            float2 f0 = __half22float2(p0[j]);
            float2 f1 = __half22float2(p1[j]);
            acc[2 * j + 0]     += w * f0.x;
            acc[2 * j + 1]     += w * f0.y;
            acc[8 + 2 * j + 0] += w * f1.x;
            acc[8 + 2 * j + 1] += w * f1.y;
        }
    }

    if (mode == 1) {
#pragma unroll
        for (int h = 0; h < 2; h++) {
            int f = h * 256 + lane * 8;
            __half2 o[4];
#pragma unroll
            for (int j = 0; j < 4; j += 1) {
                float r0 = fmaxf(acc[h * 8 + 2 * j]     + bias[f + 2 * j], 0.f);
                float r1 = fmaxf(acc[h * 8 + 2 * j + 1] + bias[f + 2 * j + 1], 0.f);
                o[j] = __floats2half2_rn(r0, r1);
            }
            *(uint4*)&g_Ah[(size_t)gw * HH + f] = *(uint4*)o;
        }
    } else {
        float a0 = 0.f, a1 = 0.f;
#pragma unroll
        for (int h = 0; h < 2; h++) {
            int f = h * 256 + lane * 8;
#pragma unroll
            for (int j = 0; j < 8; j++) {
                float rv = fmaxf(acc[h * 8 + j] + bias[f + j], 0.f);
                a0 += rv * sw[2 * (f + j) + 0];
                a1 += rv * sw[2 * (f + j) + 1];
            }
        }
#pragma unroll
        for (int off = 16; off > 0; off >>= 1) {
            a0 += __shfl_down_sync(0xFFFFFFFFu, a0, off);
            a1 += __shfl_down_sync(0xFFFFFFFFu, a1, off);
        }
        if (lane == 0) { g_t[gw * 2 + 0] = a0; g_t[gw * 2 + 1] = a1; }
    }
}

// ---------------- finalize: aggregate 2-wide + bias + log_softmax ---------------
__global__ void finalize_kernel(const float* __restrict__ b4, float* __restrict__ out)
{
    int i = blockIdx.x * blockDim.x + threadIdx.x;
    if (i >= NN) return;
    float z0 = 0.f, z1 = 0.f;
    int beg = g_rowptr[i], end = g_rowptr[i + 1];
    for (int e = beg; e < end; e++) {
        int c = g_colsrc[e];
        float w = g_w[e];
        z0 += w * g_t[2 * c + 0];
        z1 += w * g_t[2 * c + 1];
    }
    z0 += b4[0]; z1 += b4[1];
    float m = fmaxf(z0, z1);
    float lse = m + logf(expf(z0 - m) + expf(z1 - m));
    out[2 * i + 0] = z0 - lse;
    out[2 * i + 1] = z1 - lse;
}

// ---------------- launch ----------------
extern "C" void kernel_launch(void* const* d_in, const int* in_sizes, int n_in,
                              void* d_out, int out_size)
{
    const float* x  = (const float*)d_in[0];
    const int*   ei = (const int*)d_in[1];
    const float* W1 = (const float*)d_in[3];
    const float* b1 = (const float*)d_in[4];
    const float* W2 = (const float*)d_in[5];
    const float* b2 = (const float*)d_in[6];
    const float* W3 = (const float*)d_in[7];
    const float* b3 = (const float*)d_in[8];
    const float* W4 = (const float*)d_in[9];
    const float* b4 = (const float*)d_in[10];
    float* out = (float*)d_out;

    __half *pAh, *pBh1, *pBh2, *pBh3, *pH;
    int* pDeg;
    cudaGetSymbolAddress((void**)&pAh,  g_Ah);
    cudaGetSymbolAddress((void**)&pBh1, g_Bh1);
    cudaGetSymbolAddress((void**)&pBh2, g_Bh2);
    cudaGetSymbolAddress((void**)&pBh3, g_Bh3);
    cudaGetSymbolAddress((void**)&pH,   g_H);
    cudaGetSymbolAddress((void**)&pDeg, g_degi);

    const int gemm_smem = 3 * STG;     // 72 KB, opt-in (no static guard: call every time)
    cudaFuncSetAttribute(mma_gemm_kernel,
                         cudaFuncAttributeMaxDynamicSharedMemorySize, gemm_smem);

    // graph preprocessing
    cudaMemsetAsync(pDeg, 0, NN * sizeof(int));
    count_deg_kernel<<<(EE + 255) / 256, 256>>>(ei);
    scan_kernel<<<1, 1024>>>();
    fill_csr_kernel<<<(NNZ + 255) / 256, 256>>>(ei);

    dim3 gemm_grid(HH / 64, (NN + 127) / 128);     // (8, 79)
    int agg_blocks = (NN * 32 + 255) / 256;

    // conversions (all weights in one launch)
    convA_kernel<<<dim3((KP1 + 255) / 256, NN), 256>>>(x, FIN, KP1);
    convB_all_kernel<<<dim3((KP1 + 255) / 256, HH, 3), 256>>>(W1, W2, W3);

    // layer 1
    mma_gemm_kernel<<<gemm_grid, 256, gemm_smem>>>(pAh, pBh1, pH, NN, KP1);
    aggregate512_kernel<<<agg_blocks, 256>>>(pH, b1, 1, W4);
    // layer 2
    mma_gemm_kernel<<<gemm_grid, 256, gemm_smem>>>(pAh, pBh2, pH, NN, HH);
    aggregate512_kernel<<<agg_blocks, 256>>>(pH, b2, 1, W4);
    // layer 3 + fused layer-4 GEMM
    mma_gemm_kernel<<<gemm_grid, 256, gemm_smem>>>(pAh, pBh3, pH, NN, HH);
    aggregate512_kernel<<<agg_blocks, 256>>>(pH, b3, 2, W4);
    // log_softmax
    finalize_kernel<<<(NN + 255) / 256, 256>>>(b4, out);
}

// round 17
// speedup vs baseline: 1.3331x; 1.1777x over previous
#include <cuda_runtime.h>
#include <cuda_fp16.h>
#include <math.h>
#include <stdint.h>

#define NN   10000
#define EE   160000
#define FIN  2208
#define KP1  2240          // FIN padded to multiple of 64
#define HH   512
#define CC   2
#define NNZ  (EE + NN)

// ---------------- scratch (static device globals; no allocation) ----------------
__device__ float g_t[NN * CC];
__device__ int   g_degi[NN];
__device__ float g_dinv[NN];
__device__ int   g_rowptr[NN + 1];
__device__ int   g_cursor[NN];
__device__ int   g_colsrc[NNZ];
__device__ float g_w[NNZ];
__device__ __align__(16) __half g_Ah[NN * KP1];   // GEMM A operand (fp16)
__device__ __align__(16) __half g_H[NN * HH];     // GEMM fp16 output
__device__ __align__(16) __half g_Bh1[HH * KP1];  // W1^T fp16 [512][2240]
__device__ __align__(16) __half g_Bh2[HH * HH];   // W2^T fp16 [512][512]
__device__ __align__(16) __half g_Bh3[HH * HH];   // W3^T fp16 [512][512]

// ---------------- PTX helpers (sm_80-baseline, compile at compute_103) ----------
__device__ __forceinline__ uint32_t smem_u32(const void* p) {
    uint32_t a;
    asm("{ .reg .u64 t; cvta.to.shared.u64 t, %1; cvt.u32.u64 %0, t; }" : "=r"(a) : "l"(p));
    return a;
}
__device__ __forceinline__ void cpa16(uint32_t s, const void* g, int sz) {
    asm volatile("cp.async.cg.shared.global [%0], [%1], 16, %2;"
                 :: "r"(s), "l"(g), "r"(sz) : "memory");
}
__device__ __forceinline__ void cpa_commit() {
    asm volatile("cp.async.commit_group;" ::: "memory");
}
template <int N> __device__ __forceinline__ void cpa_wait() {
    asm volatile("cp.async.wait_group %0;" :: "n"(N) : "memory");
}
__device__ __forceinline__ void ldsm4(uint32_t& r0, uint32_t& r1, uint32_t& r2, uint32_t& r3,
                                      uint32_t addr) {
    asm volatile("ldmatrix.sync.aligned.m8n8.x4.shared.b16 {%0,%1,%2,%3}, [%4];"
                 : "=r"(r0), "=r"(r1), "=r"(r2), "=r"(r3) : "r"(addr));
}
__device__ __forceinline__ void mma16816(float* d, const uint32_t* a, const uint32_t* b) {
    asm volatile(
        "mma.sync.aligned.m16n8k16.row.col.f32.f16.f16.f32 "
        "{%0,%1,%2,%3}, {%4,%5,%6,%7}, {%8,%9}, {%0,%1,%2,%3};"
        : "+f"(d[0]), "+f"(d[1]), "+f"(d[2]), "+f"(d[3])
        : "r"(a[0]), "r"(a[1]), "r"(a[2]), "r"(a[3]), "r"(b[0]), "r"(b[1]));
}

// ---------------- graph preprocessing ----------------
__global__ void count_deg_kernel(const int* __restrict__ ei) {
    int e = blockIdx.x * blockDim.x + threadIdx.x;
    if (e < EE) atomicAdd(&g_degi[ei[EE + e]], 1);
}
// 1024 threads, 10 elements/thread, warp-shuffle block scan. deg = g_degi + 1 (self loop)
__global__ void scan_kernel() {
    int tid = threadIdx.x;
    int lane = tid & 31, w = tid >> 5;
    int base = tid * 10;
    int deg[10];
    int s = 0;
#pragma unroll
    for (int j = 0; j < 10; j++) {
        int i = base + j;
        deg[j] = (i < NN) ? g_degi[i] + 1 : 0;
        s += deg[j];
    }
    int inc = s;
#pragma unroll
    for (int off = 1; off < 32; off <<= 1) {
        int t = __shfl_up_sync(0xFFFFFFFFu, inc, off);
        if (lane >= off) inc += t;
    }
    __shared__ int wsum[32];
    if (lane == 31) wsum[w] = inc;
    __syncthreads();
    if (w == 0) {
        int v = wsum[lane];
        int vi = v;
#pragma unroll
        for (int off = 1; off < 32; off <<= 1) {
            int t = __shfl_up_sync(0xFFFFFFFFu, vi, off);
            if (lane >= off) vi += t;
        }
        wsum[lane] = vi - v;        // exclusive warp base
    }
    __syncthreads();
    int run = wsum[w] + inc - s;    // thread exclusive prefix
#pragma unroll
    for (int j = 0; j < 10; j++) {
        int i = base + j;
        if (i < NN) {
            g_rowptr[i] = run;
            g_cursor[i] = run;
            g_dinv[i]   = rsqrtf((float)deg[j]);
            run += deg[j];
        }
    }
    if (base < NN && base + 10 >= NN) g_rowptr[NN] = run;   // total = NNZ
}
__global__ void fill_csr_kernel(const int* __restrict__ ei) {
    int e = blockIdx.x * blockDim.x + threadIdx.x;
    if (e < EE) {
        int s = ei[e], d = ei[EE + e];
        int slot = atomicAdd(&g_cursor[d], 1);
        g_colsrc[slot] = s;
        g_w[slot] = g_dinv[s] * g_dinv[d];
    } else if (e < EE + NN) {
        int i = e - EE;
        int slot = atomicAdd(&g_cursor[i], 1);
        g_colsrc[slot] = i;
        g_w[slot] = g_dinv[i] * g_dinv[i];
    }
}

// ---------------- conversion ----------------
// A: fp32 [NN,FIN] -> fp16 [NN,KP1]; 8 elements/thread, 16B store
__global__ void convA_kernel(const float* __restrict__ src) {
    const int G = KP1 / 8;      // 280 groups per row
    int idx = blockIdx.x * blockDim.x + threadIdx.x;
    if (idx >= NN * G) return;
    int m = idx / G;
    int k = (idx - m * G) * 8;
    __half2 o[4];
    if (k < FIN) {              // FIN%8==0: group fully in-range or fully pad
        const float* p = src + (size_t)m * FIN + k;
        float4 v0 = *(const float4*)p;
        float4 v1 = *(const float4*)(p + 4);
        o[0] = __floats2half2_rn(v0.x, v0.y);
        o[1] = __floats2half2_rn(v0.z, v0.w);
        o[2] = __floats2half2_rn(v1.x, v1.y);
        o[3] = __floats2half2_rn(v1.z, v1.w);
    } else {
        o[0] = o[1] = o[2] = o[3] = __floats2half2_rn(0.f, 0.f);
    }
    *(uint4*)&g_Ah[(size_t)m * KP1 + k] = *(uint4*)o;
}
// tiled transpose W[Kin][512] fp32 -> dst[512][Kpad] fp16; z selects weight
__global__ void convB_all_kernel(const float* __restrict__ W1,
                                 const float* __restrict__ W2,
                                 const float* __restrict__ W3) {
    __shared__ float t[32][33];
    int z = blockIdx.z;
    const float* W = (z == 0) ? W1 : (z == 1) ? W2 : W3;
    __half* dst = (z == 0) ? g_Bh1 : (z == 1) ? g_Bh2 : g_Bh3;
    int Kin  = (z == 0) ? FIN : HH;
    int Kpad = (z == 0) ? KP1 : HH;
    int k0 = blockIdx.x * 32, n0 = blockIdx.y * 32;
    if (k0 >= Kpad) return;
    int tx = threadIdx.x, ty = threadIdx.y;         // 32 x 8
#pragma unroll
    for (int j = ty; j < 32; j += 8) {
        int k = k0 + j;
        t[j][tx] = (k < Kin) ? W[(size_t)k * HH + n0 + tx] : 0.f;
    }
    __syncthreads();
#pragma unroll
    for (int j = ty; j < 32; j += 8) {
        int n = n0 + j, k = k0 + tx;
        dst[(size_t)n * Kpad + k] = __float2half(t[tx][j]);
    }
}

// ---------------- MMA GEMM: H[M,512] = A @ B^T (fp16 in, fp32 acc, fp16 out) -----
// BM=128, BN=64, BK=64; 256 threads = 8 warps (4Mx2N), warp tile 32x32.
// per stage: A 16K | B 8K = 24K; 3-stage pipeline = 72K (opt-in). 2 CTAs/SM.
#define STG 24576
#define OFF_B 16384
// swizzled byte offset for (row, 16B-seg) in a 128B-pitch tile (8 segs/row)
#define SWZ(r, s) (((r) << 7) + ((((s) ^ ((r) & 7))) << 4))

__device__ __forceinline__ void issue_chunk(
    uint32_t sb, int stage, int k0, int tid, int rowBase, int colBase, int M, int Kpad,
    const __half* Ah, const __half* Bh)
{
    uint32_t st = sb + stage * STG;
#pragma unroll
    for (int s = 0; s < 4; s++) {                 // A: 1024 segs, 4/thread
        int idx = tid + s * 256;
        int r = idx >> 3, kseg = idx & 7;
        int grow = rowBase + r;
        int valid = (grow < M);
        size_t goff = (size_t)(valid ? grow : 0) * Kpad + k0 + kseg * 8;
        cpa16(st + SWZ(r, kseg), Ah + goff, valid ? 16 : 0);
    }
#pragma unroll
    for (int s = 0; s < 2; s++) {                 // B: 512 segs, 2/thread
        int idx = tid + s * 256;
        int r = idx >> 3, kseg = idx & 7;
        size_t goff = (size_t)(colBase + r) * Kpad + k0 + kseg * 8;
        cpa16(st + OFF_B + SWZ(r, kseg), Bh + goff, 16);
    }
}

__global__ __launch_bounds__(256) void mma_gemm_kernel(
    const __half* __restrict__ Ah, const __half* __restrict__ Bh,
    __half* __restrict__ H, int M, int Kpad)
{
    extern __shared__ char smem[];
    uint32_t sb = smem_u32(smem);
    int tid = threadIdx.x, lane = tid & 31, wid = tid >> 5;
    int wm = wid >> 1, wn = wid & 1;
    int rowBase = blockIdx.y * 128, colBase = blockIdx.x * 64;
    int NC = Kpad >> 6;

    float d[2][4][4];
#pragma unroll
    for (int i = 0; i < 2; i++)
#pragma unroll
        for (int j = 0; j < 4; j++)
#pragma unroll
            for (int k = 0; k < 4; k++) d[i][j][k] = 0.f;

    issue_chunk(sb, 0, 0, tid, rowBase, colBase, M, Kpad, Ah, Bh);
    cpa_commit();
    issue_chunk(sb, 1, 64, tid, rowBase, colBase, M, Kpad, Ah, Bh);
    cpa_commit();

    // per-lane ldmatrix address components (row/seg within tile)
    int a_r = (lane & 7) + (((lane >> 3) & 1) << 3);   // + mt*16 + wm*32
    int a_s = lane >> 4;                               // + ks*2
    int b_r = (lane & 7) + ((lane >> 4) << 3);         // + half*16 + wn*32
    int b_s = (lane >> 3) & 1;                         // + ks*2

    for (int i = 0; i < NC; i++) {
        if (i + 2 < NC)
            issue_chunk(sb, (i + 2) % 3, (i + 2) << 6, tid, rowBase, colBase, M, Kpad,
                        Ah, Bh);
        cpa_commit();                 // constant group accounting
        cpa_wait<2>();                // stage i complete
        __syncthreads();
        uint32_t st = sb + (i % 3) * STG;
#pragma unroll
        for (int ks = 0; ks < 4; ks++) {
            uint32_t ah[2][4], bh[4][2];
#pragma unroll
            for (int mt = 0; mt < 2; mt++) {
                int row = wm * 32 + mt * 16 + a_r;
                uint32_t off = SWZ(row, ks * 2 + a_s);
                ldsm4(ah[mt][0], ah[mt][1], ah[mt][2], ah[mt][3], st + off);
            }
#pragma unroll
            for (int h = 0; h < 2; h++) {
                int n = wn * 32 + h * 16 + b_r;
                uint32_t off = SWZ(n, ks * 2 + b_s);
                uint32_t r0, r1, r2, r3;
                ldsm4(r0, r1, r2, r3, st + OFF_B + off);
                bh[h * 2][0] = r0; bh[h * 2][1] = r1;
                bh[h * 2 + 1][0] = r2; bh[h * 2 + 1][1] = r3;
            }
#pragma unroll
            for (int mt = 0; mt < 2; mt++)
#pragma unroll
                for (int nt = 0; nt < 4; nt++)
                    mma16816(d[mt][nt], ah[mt], bh[nt]);
        }
        __syncthreads();
    }

    // epilogue: fp16 output
#pragma unroll
    for (int mt = 0; mt < 2; mt++)
#pragma unroll
        for (int nt = 0; nt < 4; nt++) {
            int rg = rowBase + wm * 32 + mt * 16 + (lane >> 2);
            int cg = colBase + wn * 32 + nt * 8 + (lane & 3) * 2;
            if (rg < M)
                *(__half2*)&H[(size_t)rg * HH + cg] = __floats2half2_rn(d[mt][nt][0], d[mt][nt][1]);
            if (rg + 8 < M)
                *(__half2*)&H[(size_t)(rg + 8) * HH + cg] = __floats2half2_rn(d[mt][nt][2], d[mt][nt][3]);
        }
}

// ---------------- aggregation: fp16 gather, fp32 acc, +bias +relu ---------------
// mode 1: write fp16 (pitch 512) to g_Ah
// mode 2: fused layer-4: t[gw] = (relu(agg + b)) @ W4   (writes g_t, not g_Ah)
__global__ __launch_bounds__(256) void aggregate512_kernel(
    const __half* __restrict__ in, const float* __restrict__ bias,
    int mode, const float* __restrict__ W4)
{
    __shared__ float sw[HH * CC];
    if (mode == 2) {
        for (int i = threadIdx.x; i < HH * CC; i += blockDim.x) sw[i] = W4[i];
        __syncthreads();
    }
    int gw = (blockIdx.x * blockDim.x + threadIdx.x) >> 5;
    int lane = threadIdx.x & 31;
    if (gw >= NN) return;
    int beg = g_rowptr[gw], end = g_rowptr[gw + 1];

    float acc[16];
#pragma unroll
    for (int j = 0; j < 16; j++) acc[j] = 0.f;

    for (int e = beg; e < end; e++) {
        int c = g_colsrc[e];
        float w = g_w[e];
        const uint4* row = (const uint4*)(in + (size_t)c * HH);
        uint4 v0 = row[lane];           // features lane*8 .. +7
        uint4 v1 = row[32 + lane];      // features 256+lane*8 .. +7
        const __half2* p0 = (const __half2*)&v0;
        const __half2* p1 = (const __half2*)&v1;
#pragma unroll
        for (int j = 0; j < 4; j++) {
            float2 f0 = __half22float2(p0[j]);
            float2 f1 = __half22float2(p1[j]);
            acc[2 * j + 0]     += w * f0.x;
            acc[2 * j + 1]     += w * f0.y;
            acc[8 + 2 * j + 0] += w * f1.x;
            acc[8 + 2 * j + 1] += w * f1.y;
        }
    }

    if (mode == 1) {
#pragma unroll
        for (int h = 0; h < 2; h++) {
            int f = h * 256 + lane * 8;
            __half2 o[4];
#pragma unroll
            for (int j = 0; j < 4; j += 1) {
                float r0 = fmaxf(acc[h * 8 + 2 * j]     + bias[f + 2 * j], 0.f);
                float r1 = fmaxf(acc[h * 8 + 2 * j + 1] + bias[f + 2 * j + 1], 0.f);
                o[j] = __floats2half2_rn(r0, r1);
            }
            *(uint4*)&g_Ah[(size_t)gw * HH + f] = *(uint4*)o;
        }
    } else {
        float a0 = 0.f, a1 = 0.f;
#pragma unroll
        for (int h = 0; h < 2; h++) {
            int f = h * 256 + lane * 8;
#pragma unroll
            for (int j = 0; j < 8; j++) {
                float rv = fmaxf(acc[h * 8 + j] + bias[f + j], 0.f);
                a0 += rv * sw[2 * (f + j) + 0];
                a1 += rv * sw[2 * (f + j) + 1];
            }
        }
#pragma unroll
        for (int off = 16; off > 0; off >>= 1) {
            a0 += __shfl_down_sync(0xFFFFFFFFu, a0, off);
            a1 += __shfl_down_sync(0xFFFFFFFFu, a1, off);
        }
        if (lane == 0) { g_t[gw * 2 + 0] = a0; g_t[gw * 2 + 1] = a1; }
    }
}

// ---------------- finalize: aggregate 2-wide + bias + log_softmax ---------------
__global__ void finalize_kernel(const float* __restrict__ b4, float* __restrict__ out)
{
    int i = blockIdx.x * blockDim.x + threadIdx.x;
    if (i >= NN) return;
    float z0 = 0.f, z1 = 0.f;
    int beg = g_rowptr[i], end = g_rowptr[i + 1];
    for (int e = beg; e < end; e++) {
        int c = g_colsrc[e];
        float w = g_w[e];
        z0 += w * g_t[2 * c + 0];
        z1 += w * g_t[2 * c + 1];
    }
    z0 += b4[0]; z1 += b4[1];
    float m = fmaxf(z0, z1);
    float lse = m + logf(expf(z0 - m) + expf(z1 - m));
    out[2 * i + 0] = z0 - lse;
    out[2 * i + 1] = z1 - lse;
}

// ---------------- launch ----------------
extern "C" void kernel_launch(void* const* d_in, const int* in_sizes, int n_in,
                              void* d_out, int out_size)
{
    const float* x  = (const float*)d_in[0];
    const int*   ei = (const int*)d_in[1];
    const float* W1 = (const float*)d_in[3];
    const float* b1 = (const float*)d_in[4];
    const float* W2 = (const float*)d_in[5];
    const float* b2 = (const float*)d_in[6];
    const float* W3 = (const float*)d_in[7];
    const float* b3 = (const float*)d_in[8];
    const float* W4 = (const float*)d_in[9];
    const float* b4 = (const float*)d_in[10];
    float* out = (float*)d_out;

    __half *pAh, *pBh1, *pBh2, *pBh3, *pH;
    int* pDeg;
    cudaGetSymbolAddress((void**)&pAh,  g_Ah);
    cudaGetSymbolAddress((void**)&pBh1, g_Bh1);
    cudaGetSymbolAddress((void**)&pBh2, g_Bh2);
    cudaGetSymbolAddress((void**)&pBh3, g_Bh3);
    cudaGetSymbolAddress((void**)&pH,   g_H);
    cudaGetSymbolAddress((void**)&pDeg, g_degi);

    const int gemm_smem = 3 * STG;     // 72 KB, opt-in (no static guard: call every time)
    cudaFuncSetAttribute(mma_gemm_kernel,
                         cudaFuncAttributeMaxDynamicSharedMemorySize, gemm_smem);

    // graph preprocessing
    cudaMemsetAsync(pDeg, 0, NN * sizeof(int));
    count_deg_kernel<<<(EE + 255) / 256, 256>>>(ei);
    scan_kernel<<<1, 1024>>>();
    fill_csr_kernel<<<(NNZ + 255) / 256, 256>>>(ei);

    dim3 gemm_grid(HH / 64, (NN + 127) / 128);     // (8, 79)
    int agg_blocks = (NN * 32 + 255) / 256;

    // conversions
    convA_kernel<<<(NN * (KP1 / 8) + 255) / 256, 256>>>(x);
    convB_all_kernel<<<dim3((KP1 + 31) / 32, HH / 32, 3), dim3(32, 8)>>>(W1, W2, W3);

    // layer 1
    mma_gemm_kernel<<<gemm_grid, 256, gemm_smem>>>(pAh, pBh1, pH, NN, KP1);
    aggregate512_kernel<<<agg_blocks, 256>>>(pH, b1, 1, W4);
    // layer 2
    mma_gemm_kernel<<<gemm_grid, 256, gemm_smem>>>(pAh, pBh2, pH, NN, HH);
    aggregate512_kernel<<<agg_blocks, 256>>>(pH, b2, 1, W4);
    // layer 3 + fused layer-4 GEMM
    mma_gemm_kernel<<<gemm_grid, 256, gemm_smem>>>(pAh, pBh3, pH, NN, HH);
    aggregate512_kernel<<<agg_blocks, 256>>>(pH, b3, 2, W4);
    // log_softmax
    finalize_kernel<<<(NN + 255) / 256, 256>>>(b4, out);
}